// round 10
// baseline (speedup 1.0000x reference)
#include <cuda_runtime.h>
#include <cstdint>

#define N_IN   256
#define N_OUT  64
#define MAXN   100000
#define MAXE   1600000

// Scratch (allocation-free rule: __device__ globals). float4 => 16B aligned.
__device__ float4 g_bufA[(size_t)MAXN * N_OUT / 4];
__device__ float4 g_bufB[(size_t)MAXN * N_OUT / 4];
__device__ float  g_WT[N_OUT * N_IN];   // W transposed: WT[n][k]
__device__ int2   g_csr[MAXE];
__device__ int    g_deg[MAXN];
__device__ int    g_rowptr[MAXN];
__device__ int    g_cursor[MAXN];
__device__ int    g_is64;

// ===================== dtype detect =========================================
__global__ void detect_dtype_kernel(const unsigned int* __restrict__ adj_words)
{
    unsigned int acc = 0;
    #pragma unroll
    for (int i = 1; i < 256; i += 2) acc |= adj_words[i];
    g_is64 = (acc == 0) ? 1 : 0;
}

__device__ __forceinline__ int load_idx(const void* adj, size_t i)
{
    return g_is64 ? (int)((const long long*)adj)[i] : ((const int*)adj)[i];
}

// ===================== CSR build (coalesced, 1 edge/thread) =================
__global__ void __launch_bounds__(256) histogram_kernel(const void* __restrict__ adj, int E)
{
    int i = blockIdx.x * blockDim.x + threadIdx.x;
    if (i >= E) return;
    atomicAdd(&g_deg[load_idx(adj, i)], 1);
}

// Single-block fused exclusive scan: deg -> rowptr + cursor.
// 1024 threads, each owns a contiguous chunk; sequential sums + block scan.
__global__ void __launch_bounds__(1024) scan_fused_kernel(int N)
{
    __shared__ int s[1024];
    const int tid = threadIdx.x;
    const int CH  = (N + 1023) / 1024;
    const int b   = tid * CH;
    const int e   = min(b + CH, N);

    int sum = 0;
    for (int i = b; i < e; i++) sum += g_deg[i];
    s[tid] = sum;
    __syncthreads();
    #pragma unroll
    for (int off = 1; off < 1024; off <<= 1) {
        int t = (tid >= off) ? s[tid - off] : 0;
        __syncthreads();
        s[tid] += t;
        __syncthreads();
    }
    int pre = s[tid] - sum;   // exclusive prefix of this chunk
    for (int i = b; i < e; i++) {
        int d = g_deg[i];
        g_rowptr[i] = pre;
        g_cursor[i] = pre;
        pre += d;
    }
}

__global__ void __launch_bounds__(256) scatter_kernel(
    const void* __restrict__ adj, const float* __restrict__ vals, int E)
{
    int i = blockIdx.x * blockDim.x + threadIdx.x;
    if (i >= E) return;
    int row = load_idx(adj, i);
    int col = load_idx(adj, (size_t)E + i);
    int pos = atomicAdd(&g_cursor[row], 1);
    g_csr[pos] = make_int2(col, __float_as_int(vals[i]));
}

// W[256][64] -> WT[64][256]
__global__ void __launch_bounds__(256) transpose_w_kernel(const float* __restrict__ W)
{
    int i = blockIdx.x * 256 + threadIdx.x;
    int n = i >> 8, k = i & 255;
    g_WT[n * N_IN + k] = W[k * N_OUT + n];
}

// ===================== tf32 mma.sync GEMM + bias + ReLU =====================
__device__ __forceinline__ uint32_t f2tf32(float f)
{
    uint32_t u;
    asm("cvt.rna.tf32.f32 %0, %1;" : "=r"(u) : "f"(f));
    return u;
}

__device__ __forceinline__ void mma_tf32(float c[4], uint32_t a0, uint32_t a1,
                                         uint32_t a2, uint32_t a3,
                                         uint32_t b0, uint32_t b1)
{
    asm volatile(
        "mma.sync.aligned.m16n8k8.row.col.f32.tf32.tf32.f32 "
        "{%0,%1,%2,%3}, {%4,%5,%6,%7}, {%8,%9}, {%0,%1,%2,%3};"
        : "+f"(c[0]), "+f"(c[1]), "+f"(c[2]), "+f"(c[3])
        : "r"(a0), "r"(a1), "r"(a2), "r"(a3), "r"(b0), "r"(b1));
}

#define XS 36   // smem row stride (uint32)

__global__ void __launch_bounds__(256) gemm_tf32_kernel(
    const float* __restrict__ X, const float* __restrict__ bias,
    float* __restrict__ out, int NN)
{
    __shared__ uint32_t sX[128 * XS];
    __shared__ uint32_t sWT[64 * XS];

    const int tid  = threadIdx.x;
    const int wid  = tid >> 5;
    const int lid  = tid & 31;
    const int gid  = lid >> 2;
    const int tig  = lid & 3;
    const int row0 = blockIdx.x * 128;
    const int wrow = wid * 16;

    float c[8][4];
    #pragma unroll
    for (int nt = 0; nt < 8; nt++)
        #pragma unroll
        for (int j = 0; j < 4; j++) c[nt][j] = 0.f;

    for (int ch = 0; ch < 8; ch++) {
        const int k0 = ch * 32;
        #pragma unroll
        for (int i = tid; i < 1024; i += 256) {
            int r = i >> 3, q = i & 7;
            float4 v = make_float4(0.f, 0.f, 0.f, 0.f);
            if (row0 + r < NN)
                v = ((const float4*)(X + (size_t)(row0 + r) * N_IN + k0))[q];
            uint4 u = make_uint4(f2tf32(v.x), f2tf32(v.y), f2tf32(v.z), f2tf32(v.w));
            *(uint4*)(sX + r * XS + q * 4) = u;
        }
        #pragma unroll
        for (int i = tid; i < 512; i += 256) {
            int n = i >> 3, q = i & 7;
            float4 v = ((const float4*)(g_WT + (size_t)n * N_IN + k0))[q];
            uint4 u = make_uint4(f2tf32(v.x), f2tf32(v.y), f2tf32(v.z), f2tf32(v.w));
            *(uint4*)(sWT + n * XS + q * 4) = u;
        }
        __syncthreads();

        #pragma unroll
        for (int ks = 0; ks < 4; ks++) {
            const int kb = ks * 8;
            uint32_t a0 = sX[(wrow + gid)     * XS + kb + tig];
            uint32_t a1 = sX[(wrow + gid + 8) * XS + kb + tig];
            uint32_t a2 = sX[(wrow + gid)     * XS + kb + tig + 4];
            uint32_t a3 = sX[(wrow + gid + 8) * XS + kb + tig + 4];
            #pragma unroll
            for (int nt = 0; nt < 8; nt++) {
                uint32_t b0 = sWT[(nt * 8 + gid) * XS + kb + tig];
                uint32_t b1 = sWT[(nt * 8 + gid) * XS + kb + tig + 4];
                mma_tf32(c[nt], a0, a1, a2, a3, b0, b1);
            }
        }
        __syncthreads();
    }

    const int row_lo = row0 + wrow + gid;
    const int row_hi = row_lo + 8;
    #pragma unroll
    for (int nt = 0; nt < 8; nt++) {
        const int col = nt * 8 + tig * 2;
        const float b0 = __ldg(bias + col);
        const float b1 = __ldg(bias + col + 1);
        if (row_lo < NN) {
            float2 o = make_float2(fmaxf(c[nt][0] + b0, 0.f),
                                   fmaxf(c[nt][1] + b1, 0.f));
            *(float2*)(out + (size_t)row_lo * N_OUT + col) = o;
        }
        if (row_hi < NN) {
            float2 o = make_float2(fmaxf(c[nt][2] + b0, 0.f),
                                   fmaxf(c[nt][3] + b1, 0.f));
            *(float2*)(out + (size_t)row_hi * N_OUT + col) = o;
        }
    }
}

// ===================== CSR SpMM (atomic-free) ===============================
__global__ void __launch_bounds__(256) spmm_csr_kernel(
    const float4* __restrict__ src, float4* __restrict__ dst, int N)
{
    const int ch  = threadIdx.x & 15;
    const int grp = threadIdx.x >> 4;
    const int row = blockIdx.x * 16 + grp;
    if (row >= N) return;

    int e   = g_rowptr[row];
    int end = g_cursor[row];

    float4 acc = make_float4(0.f, 0.f, 0.f, 0.f);

    for (; e + 4 <= end; e += 4) {
        int2 p0 = g_csr[e + 0];
        int2 p1 = g_csr[e + 1];
        int2 p2 = g_csr[e + 2];
        int2 p3 = g_csr[e + 3];
        float4 b0 = __ldg(src + (size_t)p0.x * (N_OUT / 4) + ch);
        float4 b1 = __ldg(src + (size_t)p1.x * (N_OUT / 4) + ch);
        float4 b2 = __ldg(src + (size_t)p2.x * (N_OUT / 4) + ch);
        float4 b3 = __ldg(src + (size_t)p3.x * (N_OUT / 4) + ch);
        float v0 = __int_as_float(p0.y), v1 = __int_as_float(p1.y);
        float v2 = __int_as_float(p2.y), v3 = __int_as_float(p3.y);
        acc.x += v0 * b0.x + v1 * b1.x + v2 * b2.x + v3 * b3.x;
        acc.y += v0 * b0.y + v1 * b1.y + v2 * b2.y + v3 * b3.y;
        acc.z += v0 * b0.z + v1 * b1.z + v2 * b2.z + v3 * b3.z;
        acc.w += v0 * b0.w + v1 * b1.w + v2 * b2.w + v3 * b3.w;
    }
    for (; e < end; e++) {
        int2 p = g_csr[e];
        float4 b = __ldg(src + (size_t)p.x * (N_OUT / 4) + ch);
        float v = __int_as_float(p.y);
        acc.x += v * b.x; acc.y += v * b.y; acc.z += v * b.z; acc.w += v * b.w;
    }

    dst[(size_t)row * (N_OUT / 4) + ch] = acc;
}

// ===================== launch (single linear stream) ========================
extern "C" void kernel_launch(void* const* d_in, const int* in_sizes, int n_in,
                              void* d_out, int out_size)
{
    const void*  adj  = d_in[0];
    const float* vals = (const float*)d_in[1];
    const float* X    = (const float*)d_in[2];
    const float* W    = (const float*)d_in[3];
    const float* bias = (const float*)d_in[4];
    float4*      out  = (float4*)d_out;

    const int E = in_sizes[0] / 2;
    const int N = in_sizes[2] / N_IN;

    float4* bufA = nullptr;
    float4* bufB = nullptr;
    int*    degp = nullptr;
    cudaGetSymbolAddress((void**)&bufA, g_bufA);
    cudaGetSymbolAddress((void**)&bufB, g_bufB);
    cudaGetSymbolAddress((void**)&degp, g_deg);

    // 0) dtype detect + W transpose + CSR build
    detect_dtype_kernel<<<1, 1>>>((const unsigned int*)adj);
    transpose_w_kernel<<<(N_IN * N_OUT + 255) / 256, 256>>>(W);
    cudaMemsetAsync(degp, 0, (size_t)N * sizeof(int), 0);
    histogram_kernel<<<(E + 255) / 256, 256>>>(adj, E);
    scan_fused_kernel<<<1, 1024>>>(N);
    scatter_kernel<<<(E + 255) / 256, 256>>>(adj, vals, E);

    // 1) base = relu(X @ W + b) -> bufA   (tf32 mma.sync tensor cores)
    gemm_tf32_kernel<<<(N + 127) / 128, 256>>>(X, bias, (float*)bufA, N);

    const int spmm_blocks = (N + 15) / 16;

    // 2) three atomic-free CSR SpMM hops, ping-pong
    spmm_csr_kernel<<<spmm_blocks, 256>>>(bufA, bufB, N);
    spmm_csr_kernel<<<spmm_blocks, 256>>>(bufB, bufA, N);
    spmm_csr_kernel<<<spmm_blocks, 256>>>(bufA, out, N);
}

// round 11
// speedup vs baseline: 1.9017x; 1.9017x over previous
#include <cuda_runtime.h>
#include <cstdint>

#define N_IN   256
#define N_OUT  64
#define MAXN   100000
#define MAXE   1600000
#define SCAN_BS 512
#define MAX_SCAN_BLOCKS 256

// Scratch (allocation-free rule: __device__ globals). float4 => 16B aligned.
__device__ float4 g_bufA[(size_t)MAXN * N_OUT / 4];
__device__ float4 g_bufB[(size_t)MAXN * N_OUT / 4];
__device__ float  g_WT[N_OUT * N_IN];   // W transposed: WT[n][k]
__device__ int2   g_csr[MAXE];
__device__ int    g_deg[MAXN];
__device__ int    g_scanInc[MAXN];
__device__ int    g_rowptr[MAXN];
__device__ int    g_cursor[MAXN];
__device__ int    g_blockSums[MAX_SCAN_BLOCKS];
__device__ int    g_blockOff[MAX_SCAN_BLOCKS];
__device__ int    g_is64;

// ===================== dtype detect + CSR build =============================
__global__ void detect_dtype_kernel(const unsigned int* __restrict__ adj_words)
{
    unsigned int acc = 0;
    #pragma unroll
    for (int i = 1; i < 256; i += 2) acc |= adj_words[i];
    g_is64 = (acc == 0) ? 1 : 0;
}

__device__ __forceinline__ int load_idx(const void* adj, size_t i)
{
    return g_is64 ? (int)((const long long*)adj)[i] : ((const int*)adj)[i];
}

__global__ void __launch_bounds__(256) histogram_kernel(const void* __restrict__ adj, int E)
{
    int i = blockIdx.x * blockDim.x + threadIdx.x;
    if (i >= E) return;
    atomicAdd(&g_deg[load_idx(adj, i)], 1);
}

__global__ void __launch_bounds__(SCAN_BS) scan1_kernel(int N)
{
    __shared__ int s[SCAN_BS];
    int i = blockIdx.x * SCAN_BS + threadIdx.x;
    int v = (i < N) ? g_deg[i] : 0;
    s[threadIdx.x] = v;
    __syncthreads();
    #pragma unroll
    for (int off = 1; off < SCAN_BS; off <<= 1) {
        int t = (threadIdx.x >= off) ? s[threadIdx.x - off] : 0;
        __syncthreads();
        s[threadIdx.x] += t;
        __syncthreads();
    }
    if (i < N) g_scanInc[i] = s[threadIdx.x];
    if (threadIdx.x == SCAN_BS - 1) g_blockSums[blockIdx.x] = s[SCAN_BS - 1];
}

__global__ void __launch_bounds__(MAX_SCAN_BLOCKS) scan2_kernel(int NB)
{
    __shared__ int s[MAX_SCAN_BLOCKS];
    int v = (threadIdx.x < NB) ? g_blockSums[threadIdx.x] : 0;
    s[threadIdx.x] = v;
    __syncthreads();
    #pragma unroll
    for (int off = 1; off < MAX_SCAN_BLOCKS; off <<= 1) {
        int t = (threadIdx.x >= off) ? s[threadIdx.x - off] : 0;
        __syncthreads();
        s[threadIdx.x] += t;
        __syncthreads();
    }
    g_blockOff[threadIdx.x] = s[threadIdx.x] - v;
}

__global__ void __launch_bounds__(256) scan3_kernel(int N)
{
    int i = blockIdx.x * 256 + threadIdx.x;
    if (i < N) {
        int excl = g_scanInc[i] - g_deg[i] + g_blockOff[i >> 9];
        g_rowptr[i] = excl;
        g_cursor[i] = excl;
    }
}

__global__ void __launch_bounds__(256) scatter_kernel(
    const void* __restrict__ adj, const float* __restrict__ vals, int E)
{
    int i = blockIdx.x * blockDim.x + threadIdx.x;
    if (i >= E) return;
    int row = load_idx(adj, i);
    int col = load_idx(adj, (size_t)E + i);
    int pos = atomicAdd(&g_cursor[row], 1);
    g_csr[pos] = make_int2(col, __float_as_int(vals[i]));
}

// W[256][64] -> WT[64][256]
__global__ void __launch_bounds__(256) transpose_w_kernel(const float* __restrict__ W)
{
    int i = blockIdx.x * 256 + threadIdx.x;
    int n = i >> 8, k = i & 255;
    g_WT[n * N_IN + k] = W[k * N_OUT + n];
}

// ===================== tf32 mma.sync GEMM + bias + ReLU =====================
__device__ __forceinline__ uint32_t f2tf32(float f)
{
    uint32_t u;
    asm("cvt.rna.tf32.f32 %0, %1;" : "=r"(u) : "f"(f));
    return u;
}

__device__ __forceinline__ void mma_tf32(float c[4], uint32_t a0, uint32_t a1,
                                         uint32_t a2, uint32_t a3,
                                         uint32_t b0, uint32_t b1)
{
    asm volatile(
        "mma.sync.aligned.m16n8k8.row.col.f32.tf32.tf32.f32 "
        "{%0,%1,%2,%3}, {%4,%5,%6,%7}, {%8,%9}, {%0,%1,%2,%3};"
        : "+f"(c[0]), "+f"(c[1]), "+f"(c[2]), "+f"(c[3])
        : "r"(a0), "r"(a1), "r"(a2), "r"(a3), "r"(b0), "r"(b1));
}

#define XS 36   // smem row stride (uint32)

__global__ void __launch_bounds__(256) gemm_tf32_kernel(
    const float* __restrict__ X, const float* __restrict__ bias,
    float* __restrict__ out, int NN)
{
    __shared__ uint32_t sX[128 * XS];
    __shared__ uint32_t sWT[64 * XS];

    const int tid  = threadIdx.x;
    const int wid  = tid >> 5;
    const int lid  = tid & 31;
    const int gid  = lid >> 2;
    const int tig  = lid & 3;
    const int row0 = blockIdx.x * 128;
    const int wrow = wid * 16;

    float c[8][4];
    #pragma unroll
    for (int nt = 0; nt < 8; nt++)
        #pragma unroll
        for (int j = 0; j < 4; j++) c[nt][j] = 0.f;

    for (int ch = 0; ch < 8; ch++) {
        const int k0 = ch * 32;
        #pragma unroll
        for (int i = tid; i < 1024; i += 256) {
            int r = i >> 3, q = i & 7;
            float4 v = make_float4(0.f, 0.f, 0.f, 0.f);
            if (row0 + r < NN)
                v = ((const float4*)(X + (size_t)(row0 + r) * N_IN + k0))[q];
            uint4 u = make_uint4(f2tf32(v.x), f2tf32(v.y), f2tf32(v.z), f2tf32(v.w));
            *(uint4*)(sX + r * XS + q * 4) = u;
        }
        #pragma unroll
        for (int i = tid; i < 512; i += 256) {
            int n = i >> 3, q = i & 7;
            float4 v = ((const float4*)(g_WT + (size_t)n * N_IN + k0))[q];
            uint4 u = make_uint4(f2tf32(v.x), f2tf32(v.y), f2tf32(v.z), f2tf32(v.w));
            *(uint4*)(sWT + n * XS + q * 4) = u;
        }
        __syncthreads();

        #pragma unroll
        for (int ks = 0; ks < 4; ks++) {
            const int kb = ks * 8;
            uint32_t a0 = sX[(wrow + gid)     * XS + kb + tig];
            uint32_t a1 = sX[(wrow + gid + 8) * XS + kb + tig];
            uint32_t a2 = sX[(wrow + gid)     * XS + kb + tig + 4];
            uint32_t a3 = sX[(wrow + gid + 8) * XS + kb + tig + 4];
            #pragma unroll
            for (int nt = 0; nt < 8; nt++) {
                uint32_t b0 = sWT[(nt * 8 + gid) * XS + kb + tig];
                uint32_t b1 = sWT[(nt * 8 + gid) * XS + kb + tig + 4];
                mma_tf32(c[nt], a0, a1, a2, a3, b0, b1);
            }
        }
        __syncthreads();
    }

    const int row_lo = row0 + wrow + gid;
    const int row_hi = row_lo + 8;
    #pragma unroll
    for (int nt = 0; nt < 8; nt++) {
        const int col = nt * 8 + tig * 2;
        const float b0 = __ldg(bias + col);
        const float b1 = __ldg(bias + col + 1);
        if (row_lo < NN) {
            float2 o = make_float2(fmaxf(c[nt][0] + b0, 0.f),
                                   fmaxf(c[nt][1] + b1, 0.f));
            *(float2*)(out + (size_t)row_lo * N_OUT + col) = o;
        }
        if (row_hi < NN) {
            float2 o = make_float2(fmaxf(c[nt][2] + b0, 0.f),
                                   fmaxf(c[nt][3] + b1, 0.f));
            *(float2*)(out + (size_t)row_hi * N_OUT + col) = o;
        }
    }
}

// ===================== CSR SpMM (atomic-free) ===============================
__global__ void __launch_bounds__(256) spmm_csr_kernel(
    const float4* __restrict__ src, float4* __restrict__ dst, int N)
{
    const int ch  = threadIdx.x & 15;
    const int grp = threadIdx.x >> 4;
    const int row = blockIdx.x * 16 + grp;
    if (row >= N) return;

    int e   = g_rowptr[row];
    int end = g_cursor[row];

    float4 acc = make_float4(0.f, 0.f, 0.f, 0.f);

    for (; e + 4 <= end; e += 4) {
        int2 p0 = g_csr[e + 0];
        int2 p1 = g_csr[e + 1];
        int2 p2 = g_csr[e + 2];
        int2 p3 = g_csr[e + 3];
        float4 b0 = __ldg(src + (size_t)p0.x * (N_OUT / 4) + ch);
        float4 b1 = __ldg(src + (size_t)p1.x * (N_OUT / 4) + ch);
        float4 b2 = __ldg(src + (size_t)p2.x * (N_OUT / 4) + ch);
        float4 b3 = __ldg(src + (size_t)p3.x * (N_OUT / 4) + ch);
        float v0 = __int_as_float(p0.y), v1 = __int_as_float(p1.y);
        float v2 = __int_as_float(p2.y), v3 = __int_as_float(p3.y);
        acc.x += v0 * b0.x + v1 * b1.x + v2 * b2.x + v3 * b3.x;
        acc.y += v0 * b0.y + v1 * b1.y + v2 * b2.y + v3 * b3.y;
        acc.z += v0 * b0.z + v1 * b1.z + v2 * b2.z + v3 * b3.z;
        acc.w += v0 * b0.w + v1 * b1.w + v2 * b2.w + v3 * b3.w;
    }
    for (; e < end; e++) {
        int2 p = g_csr[e];
        float4 b = __ldg(src + (size_t)p.x * (N_OUT / 4) + ch);
        float v = __int_as_float(p.y);
        acc.x += v * b.x; acc.y += v * b.y; acc.z += v * b.z; acc.w += v * b.w;
    }

    dst[(size_t)row * (N_OUT / 4) + ch] = acc;
}

// ===================== launch ===============================================
// Main stream: detect -> memset -> histogram -> scan x3 -> scatter --\
// Side  s2:   transpose -> GEMM --------------------------------- join -> spmm x3
extern "C" void kernel_launch(void* const* d_in, const int* in_sizes, int n_in,
                              void* d_out, int out_size)
{
    const void*  adj  = d_in[0];
    const float* vals = (const float*)d_in[1];
    const float* X    = (const float*)d_in[2];
    const float* W    = (const float*)d_in[3];
    const float* bias = (const float*)d_in[4];
    float4*      out  = (float4*)d_out;

    const int E = in_sizes[0] / 2;
    const int N = in_sizes[2] / N_IN;

    float4* bufA = nullptr;
    float4* bufB = nullptr;
    int*    degp = nullptr;
    cudaGetSymbolAddress((void**)&bufA, g_bufA);
    cudaGetSymbolAddress((void**)&bufB, g_bufB);
    cudaGetSymbolAddress((void**)&degp, g_deg);

    // One-time host objects (no device memory involved).
    static cudaStream_t s2 = nullptr;
    static cudaEvent_t evFork = nullptr, evJoin = nullptr;
    if (!s2) {
        cudaStreamCreate(&s2);
        cudaEventCreateWithFlags(&evFork, cudaEventDisableTiming);
        cudaEventCreateWithFlags(&evJoin, cudaEventDisableTiming);
    }

    // Fork side branch off stream 0.
    cudaEventRecord(evFork, 0);
    cudaStreamWaitEvent(s2, evFork, 0);

    // Side branch: W transpose -> tf32 GEMM -> bufA
    transpose_w_kernel<<<(N_IN * N_OUT + 255) / 256, 256, 0, s2>>>(W);
    gemm_tf32_kernel<<<(N + 127) / 128, 256, 0, s2>>>(X, bias, (float*)bufA, N);
    cudaEventRecord(evJoin, s2);

    // Main branch: CSR build (R8-proven kernels)
    detect_dtype_kernel<<<1, 1>>>((const unsigned int*)adj);
    cudaMemsetAsync(degp, 0, (size_t)N * sizeof(int), 0);
    histogram_kernel<<<(E + 255) / 256, 256>>>(adj, E);
    const int NB = (N + SCAN_BS - 1) / SCAN_BS;
    scan1_kernel<<<NB, SCAN_BS>>>(N);
    scan2_kernel<<<1, MAX_SCAN_BLOCKS>>>(NB);
    scan3_kernel<<<(N + 255) / 256, 256>>>(N);
    scatter_kernel<<<(E + 255) / 256, 256>>>(adj, vals, E);

    // Join: SpMM needs both bufA (GEMM) and CSR.
    cudaStreamWaitEvent(0, evJoin, 0);

    const int spmm_blocks = (N + 15) / 16;
    spmm_csr_kernel<<<spmm_blocks, 256>>>(bufA, bufB, N);
    spmm_csr_kernel<<<spmm_blocks, 256>>>(bufB, bufA, N);
    spmm_csr_kernel<<<spmm_blocks, 256>>>(bufA, out, N);
}

// round 12
// speedup vs baseline: 1.9808x; 1.0416x over previous
#include <cuda_runtime.h>
#include <cstdint>

#define N_IN   256
#define N_OUT  64
#define MAXN   100000
#define MAXE   1600000
#define SCAN_BS 512
#define MAX_SCAN_BLOCKS 256

// Scratch (allocation-free rule: __device__ globals). float4 => 16B aligned.
__device__ float4 g_bufA[(size_t)MAXN * N_OUT / 4];
__device__ float4 g_bufB[(size_t)MAXN * N_OUT / 4];
__device__ float  g_WT[N_OUT * N_IN];   // W transposed: WT[n][k]
__device__ int2   g_csr[MAXE];
__device__ int    g_deg[MAXN];
__device__ int    g_scanInc[MAXN];
__device__ int    g_rowptr[MAXN];
__device__ int    g_cursor[MAXN];
__device__ int    g_blockSums[MAX_SCAN_BLOCKS];
__device__ int    g_blockOff[MAX_SCAN_BLOCKS];
__device__ int    g_is64;

// ===================== dtype detect + CSR build =============================
__global__ void detect_dtype_kernel(const unsigned int* __restrict__ adj_words)
{
    unsigned int acc = 0;
    #pragma unroll
    for (int i = 1; i < 256; i += 2) acc |= adj_words[i];
    g_is64 = (acc == 0) ? 1 : 0;
}

__device__ __forceinline__ int load_idx(const void* adj, size_t i)
{
    return g_is64 ? (int)((const long long*)adj)[i] : ((const int*)adj)[i];
}

// Histogram: 2 edges/thread via one coalesced 16B (int64) / 8B (int32) row load.
__global__ void __launch_bounds__(256) histogram_kernel(const void* __restrict__ adj, int E)
{
    const int base = (blockIdx.x * 256 + threadIdx.x) * 2;
    if (base >= E) return;
    if (g_is64) {
        const ulonglong2 rr = ((const ulonglong2*)adj)[base >> 1];   // rows[base], rows[base+1]
        atomicAdd(&g_deg[(int)rr.x], 1);
        if (base + 1 < E) atomicAdd(&g_deg[(int)rr.y], 1);
    } else {
        const int2 rr = ((const int2*)adj)[base >> 1];
        atomicAdd(&g_deg[rr.x], 1);
        if (base + 1 < E) atomicAdd(&g_deg[rr.y], 1);
    }
}

__global__ void __launch_bounds__(SCAN_BS) scan1_kernel(int N)
{
    __shared__ int s[SCAN_BS];
    int i = blockIdx.x * SCAN_BS + threadIdx.x;
    int v = (i < N) ? g_deg[i] : 0;
    s[threadIdx.x] = v;
    __syncthreads();
    #pragma unroll
    for (int off = 1; off < SCAN_BS; off <<= 1) {
        int t = (threadIdx.x >= off) ? s[threadIdx.x - off] : 0;
        __syncthreads();
        s[threadIdx.x] += t;
        __syncthreads();
    }
    if (i < N) g_scanInc[i] = s[threadIdx.x];
    if (threadIdx.x == SCAN_BS - 1) g_blockSums[blockIdx.x] = s[SCAN_BS - 1];
}

__global__ void __launch_bounds__(MAX_SCAN_BLOCKS) scan2_kernel(int NB)
{
    __shared__ int s[MAX_SCAN_BLOCKS];
    int v = (threadIdx.x < NB) ? g_blockSums[threadIdx.x] : 0;
    s[threadIdx.x] = v;
    __syncthreads();
    #pragma unroll
    for (int off = 1; off < MAX_SCAN_BLOCKS; off <<= 1) {
        int t = (threadIdx.x >= off) ? s[threadIdx.x - off] : 0;
        __syncthreads();
        s[threadIdx.x] += t;
        __syncthreads();
    }
    g_blockOff[threadIdx.x] = s[threadIdx.x] - v;
}

__global__ void __launch_bounds__(256) scan3_kernel(int N)
{
    int i = blockIdx.x * 256 + threadIdx.x;
    if (i < N) {
        int excl = g_scanInc[i] - g_deg[i] + g_blockOff[i >> 9];
        g_rowptr[i] = excl;
        g_cursor[i] = excl;
    }
}

// Scatter: 2 edges/thread; rows via vector load, cols scalar (offset E may be odd-aligned).
__global__ void __launch_bounds__(256) scatter_kernel(
    const void* __restrict__ adj, const float* __restrict__ vals, int E)
{
    const int base = (blockIdx.x * 256 + threadIdx.x) * 2;
    if (base >= E) return;
    int r0, r1 = -1, c0, c1 = 0;
    if (g_is64) {
        const ulonglong2 rr = ((const ulonglong2*)adj)[base >> 1];
        const long long* a = (const long long*)adj;
        r0 = (int)rr.x;
        c0 = (int)a[(size_t)E + base];
        if (base + 1 < E) { r1 = (int)rr.y; c1 = (int)a[(size_t)E + base + 1]; }
    } else {
        const int2 rr = ((const int2*)adj)[base >> 1];
        const int* a = (const int*)adj;
        r0 = rr.x;
        c0 = a[E + base];
        if (base + 1 < E) { r1 = rr.y; c1 = a[E + base + 1]; }
    }
    const float2 vv = ((const float2*)vals)[base >> 1];   // 8B aligned (base even)
    int p0 = atomicAdd(&g_cursor[r0], 1);
    g_csr[p0] = make_int2(c0, __float_as_int(vv.x));
    if (r1 >= 0) {
        int p1 = atomicAdd(&g_cursor[r1], 1);
        g_csr[p1] = make_int2(c1, __float_as_int(vv.y));
    }
}

// W[256][64] -> WT[64][256]
__global__ void __launch_bounds__(256) transpose_w_kernel(const float* __restrict__ W)
{
    int i = blockIdx.x * 256 + threadIdx.x;
    int n = i >> 8, k = i & 255;
    g_WT[n * N_IN + k] = W[k * N_OUT + n];
}

// ===================== tf32 mma.sync GEMM + bias + ReLU =====================
__device__ __forceinline__ uint32_t f2tf32(float f)
{
    uint32_t u;
    asm("cvt.rna.tf32.f32 %0, %1;" : "=r"(u) : "f"(f));
    return u;
}

__device__ __forceinline__ void mma_tf32(float c[4], uint32_t a0, uint32_t a1,
                                         uint32_t a2, uint32_t a3,
                                         uint32_t b0, uint32_t b1)
{
    asm volatile(
        "mma.sync.aligned.m16n8k8.row.col.f32.tf32.tf32.f32 "
        "{%0,%1,%2,%3}, {%4,%5,%6,%7}, {%8,%9}, {%0,%1,%2,%3};"
        : "+f"(c[0]), "+f"(c[1]), "+f"(c[2]), "+f"(c[3])
        : "r"(a0), "r"(a1), "r"(a2), "r"(a3), "r"(b0), "r"(b1));
}

#define XS 36   // smem row stride (uint32)

__global__ void __launch_bounds__(256) gemm_tf32_kernel(
    const float* __restrict__ X, const float* __restrict__ bias,
    float* __restrict__ out, int NN)
{
    __shared__ uint32_t sX[128 * XS];
    __shared__ uint32_t sWT[64 * XS];

    const int tid  = threadIdx.x;
    const int wid  = tid >> 5;
    const int lid  = tid & 31;
    const int gid  = lid >> 2;
    const int tig  = lid & 3;
    const int row0 = blockIdx.x * 128;
    const int wrow = wid * 16;

    float c[8][4];
    #pragma unroll
    for (int nt = 0; nt < 8; nt++)
        #pragma unroll
        for (int j = 0; j < 4; j++) c[nt][j] = 0.f;

    for (int ch = 0; ch < 8; ch++) {
        const int k0 = ch * 32;
        #pragma unroll
        for (int i = tid; i < 1024; i += 256) {
            int r = i >> 3, q = i & 7;
            float4 v = make_float4(0.f, 0.f, 0.f, 0.f);
            if (row0 + r < NN)
                v = ((const float4*)(X + (size_t)(row0 + r) * N_IN + k0))[q];
            uint4 u = make_uint4(f2tf32(v.x), f2tf32(v.y), f2tf32(v.z), f2tf32(v.w));
            *(uint4*)(sX + r * XS + q * 4) = u;
        }
        #pragma unroll
        for (int i = tid; i < 512; i += 256) {
            int n = i >> 3, q = i & 7;
            float4 v = ((const float4*)(g_WT + (size_t)n * N_IN + k0))[q];
            uint4 u = make_uint4(f2tf32(v.x), f2tf32(v.y), f2tf32(v.z), f2tf32(v.w));
            *(uint4*)(sWT + n * XS + q * 4) = u;
        }
        __syncthreads();

        #pragma unroll
        for (int ks = 0; ks < 4; ks++) {
            const int kb = ks * 8;
            uint32_t a0 = sX[(wrow + gid)     * XS + kb + tig];
            uint32_t a1 = sX[(wrow + gid + 8) * XS + kb + tig];
            uint32_t a2 = sX[(wrow + gid)     * XS + kb + tig + 4];
            uint32_t a3 = sX[(wrow + gid + 8) * XS + kb + tig + 4];
            #pragma unroll
            for (int nt = 0; nt < 8; nt++) {
                uint32_t b0 = sWT[(nt * 8 + gid) * XS + kb + tig];
                uint32_t b1 = sWT[(nt * 8 + gid) * XS + kb + tig + 4];
                mma_tf32(c[nt], a0, a1, a2, a3, b0, b1);
            }
        }
        __syncthreads();
    }

    const int row_lo = row0 + wrow + gid;
    const int row_hi = row_lo + 8;
    #pragma unroll
    for (int nt = 0; nt < 8; nt++) {
        const int col = nt * 8 + tig * 2;
        const float b0 = __ldg(bias + col);
        const float b1 = __ldg(bias + col + 1);
        if (row_lo < NN) {
            float2 o = make_float2(fmaxf(c[nt][0] + b0, 0.f),
                                   fmaxf(c[nt][1] + b1, 0.f));
            *(float2*)(out + (size_t)row_lo * N_OUT + col) = o;
        }
        if (row_hi < NN) {
            float2 o = make_float2(fmaxf(c[nt][2] + b0, 0.f),
                                   fmaxf(c[nt][3] + b1, 0.f));
            *(float2*)(out + (size_t)row_hi * N_OUT + col) = o;
        }
    }
}

// ===================== CSR SpMM (atomic-free, MLP=8) ========================
__global__ void __launch_bounds__(256) spmm_csr_kernel(
    const float4* __restrict__ src, float4* __restrict__ dst, int N)
{
    const int ch  = threadIdx.x & 15;
    const int grp = threadIdx.x >> 4;
    const int row = blockIdx.x * 16 + grp;
    if (row >= N) return;

    int e   = g_rowptr[row];
    int end = g_cursor[row];

    float4 acc = make_float4(0.f, 0.f, 0.f, 0.f);

    for (; e + 8 <= end; e += 8) {
        int2 p[8];
        #pragma unroll
        for (int j = 0; j < 8; j++) p[j] = g_csr[e + j];
        float4 b[8];
        #pragma unroll
        for (int j = 0; j < 8; j++)
            b[j] = __ldg(src + (size_t)p[j].x * (N_OUT / 4) + ch);
        #pragma unroll
        for (int j = 0; j < 8; j++) {
            float v = __int_as_float(p[j].y);
            acc.x += v * b[j].x; acc.y += v * b[j].y;
            acc.z += v * b[j].z; acc.w += v * b[j].w;
        }
    }
    for (; e + 4 <= end; e += 4) {
        int2 p[4];
        #pragma unroll
        for (int j = 0; j < 4; j++) p[j] = g_csr[e + j];
        float4 b[4];
        #pragma unroll
        for (int j = 0; j < 4; j++)
            b[j] = __ldg(src + (size_t)p[j].x * (N_OUT / 4) + ch);
        #pragma unroll
        for (int j = 0; j < 4; j++) {
            float v = __int_as_float(p[j].y);
            acc.x += v * b[j].x; acc.y += v * b[j].y;
            acc.z += v * b[j].z; acc.w += v * b[j].w;
        }
    }
    for (; e < end; e++) {
        int2 p = g_csr[e];
        float4 b = __ldg(src + (size_t)p.x * (N_OUT / 4) + ch);
        float v = __int_as_float(p.y);
        acc.x += v * b.x; acc.y += v * b.y; acc.z += v * b.z; acc.w += v * b.w;
    }

    dst[(size_t)row * (N_OUT / 4) + ch] = acc;
}

// ===================== launch ===============================================
// Main stream: detect -> memset -> histogram -> scan x3 -> scatter --\
// Side  s2:   transpose -> GEMM --------------------------------- join -> spmm x3
extern "C" void kernel_launch(void* const* d_in, const int* in_sizes, int n_in,
                              void* d_out, int out_size)
{
    const void*  adj  = d_in[0];
    const float* vals = (const float*)d_in[1];
    const float* X    = (const float*)d_in[2];
    const float* W    = (const float*)d_in[3];
    const float* bias = (const float*)d_in[4];
    float4*      out  = (float4*)d_out;

    const int E = in_sizes[0] / 2;
    const int N = in_sizes[2] / N_IN;

    float4* bufA = nullptr;
    float4* bufB = nullptr;
    int*    degp = nullptr;
    cudaGetSymbolAddress((void**)&bufA, g_bufA);
    cudaGetSymbolAddress((void**)&bufB, g_bufB);
    cudaGetSymbolAddress((void**)&degp, g_deg);

    // One-time host objects (no device memory involved).
    static cudaStream_t s2 = nullptr;
    static cudaEvent_t evFork = nullptr, evJoin = nullptr;
    if (!s2) {
        cudaStreamCreate(&s2);
        cudaEventCreateWithFlags(&evFork, cudaEventDisableTiming);
        cudaEventCreateWithFlags(&evJoin, cudaEventDisableTiming);
    }

    // Fork side branch off stream 0.
    cudaEventRecord(evFork, 0);
    cudaStreamWaitEvent(s2, evFork, 0);

    // Side branch: W transpose -> tf32 GEMM -> bufA
    transpose_w_kernel<<<(N_IN * N_OUT + 255) / 256, 256, 0, s2>>>(W);
    gemm_tf32_kernel<<<(N + 127) / 128, 256, 0, s2>>>(X, bias, (float*)bufA, N);
    cudaEventRecord(evJoin, s2);

    // Main branch: CSR build
    detect_dtype_kernel<<<1, 1>>>((const unsigned int*)adj);
    cudaMemsetAsync(degp, 0, (size_t)N * sizeof(int), 0);
    const int eb2 = (E + 511) / 512;   // 2 edges/thread blocks
    histogram_kernel<<<eb2, 256>>>(adj, E);
    const int NB = (N + SCAN_BS - 1) / SCAN_BS;
    scan1_kernel<<<NB, SCAN_BS>>>(N);
    scan2_kernel<<<1, MAX_SCAN_BLOCKS>>>(NB);
    scan3_kernel<<<(N + 255) / 256, 256>>>(N);
    scatter_kernel<<<eb2, 256>>>(adj, vals, E);

    // Join: SpMM needs both bufA (GEMM) and CSR.
    cudaStreamWaitEvent(0, evJoin, 0);

    const int spmm_blocks = (N + 15) / 16;
    spmm_csr_kernel<<<spmm_blocks, 256>>>(bufA, bufB, N);
    spmm_csr_kernel<<<spmm_blocks, 256>>>(bufB, bufA, N);
    spmm_csr_kernel<<<spmm_blocks, 256>>>(bufA, out, N);
}